// round 16
// baseline (speedup 1.0000x reference)
#include <cuda_runtime.h>
#include <cuda_fp16.h>
#include <math.h>
#include <stdint.h>
#include <string.h>

// Problem constants
constexpr int Bb = 4;
constexpr int Tt = 512;
constexpr int BT = Bb * Tt;          // 2048
constexpr int Dd = 768;
constexpr int Hh = 12;
constexpr int HD = 64;
constexpr int Ll = 6;
constexpr int Vv = 50257;
constexpr int VP = 50432;            // padded vocab cols (mult of 128)
constexpr int FF = 4 * Dd;           // 3072
constexpr int QS = 3 * Dd;           // 2304
constexpr int NPART = 2 * (VP / 128);   // 788 lse partials per row
constexpr float EPS = 1e-5f;

// ---------------- static scratch ----------------
__device__ float  g_x[BT * Dd];
__device__ __half g_ln16[BT * Dd];
__device__ __half g_h16[BT * Dd];
__device__ __half g_qkv16[(size_t)BT * QS];
__device__ __half g_attn16[BT * Dd];
__device__ __half g_ff16[(size_t)BT * FF];
__device__ __half g_x16[BT * Dd];
__device__ __half g_wT16[(size_t)Ll * Dd * QS];
__device__ __half g_ipw16[(size_t)Ll * Dd * Dd];
__device__ __half g_opw16[(size_t)Ll * Dd * Dd];
__device__ __half g_w116[(size_t)Ll * Dd * FF];
__device__ __half g_w216[(size_t)Ll * FF * Dd];
__device__ __half g_wpad16[(size_t)Dd * VP];
__device__ float  g_bqkv[Ll * QS];
__device__ float  g_part[(size_t)BT * NPART];
__device__ float  g_nll[BT];
__device__ float  g_logits_fb[(size_t)BT * Vv];

// ---------------- PTX helpers ----------------
__device__ __forceinline__ uint32_t smem_u32(const void* p) {
    uint32_t a;
    asm("{ .reg .u64 t; cvta.to.shared.u64 t, %1; cvt.u32.u64 %0, t; }"
        : "=r"(a) : "l"(p));
    return a;
}
__device__ __forceinline__ uint32_t h2u(__half2 h) {
    uint32_t u;
    memcpy(&u, &h, 4);
    return u;
}
__device__ __forceinline__ void cp16(uint32_t s, const void* g) {
    asm volatile("cp.async.cg.shared.global [%0], [%1], 16;" :: "r"(s), "l"(g));
}
#define CP_COMMIT() asm volatile("cp.async.commit_group;" ::: "memory")
template <int N>
__device__ __forceinline__ void cp_wait() {
    asm volatile("cp.async.wait_group %0;" :: "n"(N) : "memory");
}
__device__ __forceinline__ void mma_f16(float* c, const uint32_t* a, const uint32_t* b) {
    asm volatile(
        "mma.sync.aligned.m16n8k16.row.col.f32.f16.f16.f32 "
        "{%0,%1,%2,%3}, {%4,%5,%6,%7}, {%8,%9}, {%0,%1,%2,%3};"
        : "+f"(c[0]), "+f"(c[1]), "+f"(c[2]), "+f"(c[3])
        : "r"(a[0]), "r"(a[1]), "r"(a[2]), "r"(a[3]), "r"(b[0]), "r"(b[1]));
}
#define LDSM_X4(r, addr) \
    asm volatile("ldmatrix.sync.aligned.m8n8.x4.shared.b16 {%0,%1,%2,%3}, [%4];" \
        : "=r"((r)[0]), "=r"((r)[1]), "=r"((r)[2]), "=r"((r)[3]) : "r"(addr))
#define LDSM_X4T(r, addr) \
    asm volatile("ldmatrix.sync.aligned.m8n8.x4.trans.shared.b16 {%0,%1,%2,%3}, [%4];" \
        : "=r"((r)[0]), "=r"((r)[1]), "=r"((r)[2]), "=r"((r)[3]) : "r"(addr))

// ---------------- embedding ----------------
__global__ void embed_kernel(const int* __restrict__ x,
                             const float* __restrict__ tok,
                             const float* __restrict__ pos,
                             float* __restrict__ out) {
    int row = blockIdx.x;
    int id = x[row];
    int t = row % Tt;
    const float* tp = tok + (size_t)id * Dd;
    const float* pp = pos + (size_t)t * Dd;
    float* op = out + (size_t)row * Dd;
    for (int d = threadIdx.x; d < Dd; d += blockDim.x)
        op[d] = tp[d] + pp[d];
}

// ---------------- all-weights convert: 4 contiguous regions, one launch ----------------
constexpr int WSZ1 = Ll * Dd * Dd / 16;
constexpr int WSZ2 = Ll * Dd * FF / 16;
__global__ void cvt_all_kernel(const float* __restrict__ s0, __half* __restrict__ d0,
                               const float* __restrict__ s1, __half* __restrict__ d1,
                               const float* __restrict__ s2, __half* __restrict__ d2,
                               const float* __restrict__ s3, __half* __restrict__ d3) {
    int i = blockIdx.x * blockDim.x + threadIdx.x;
    const float* src;
    __half* dst;
    int r;
    if (i < WSZ1) { src = s0; dst = d0; r = i; }
    else if (i < 2 * WSZ1) { src = s1; dst = d1; r = i - WSZ1; }
    else if (i < 2 * WSZ1 + WSZ2) { src = s2; dst = d2; r = i - 2 * WSZ1; }
    else if (i < 2 * WSZ1 + 2 * WSZ2) { src = s3; dst = d3; r = i - 2 * WSZ1 - WSZ2; }
    else return;
#pragma unroll
    for (int j = 0; j < 4; j++) {
        float4 a = *reinterpret_cast<const float4*>(src + (size_t)r * 16 + j * 4);
        __half2 h0 = __floats2half2_rn(a.x, a.y);
        __half2 h1 = __floats2half2_rn(a.z, a.w);
        *reinterpret_cast<uint2*>(dst + (size_t)r * 16 + j * 4) =
            make_uint2(h2u(h0), h2u(h1));
    }
}

// ---------------- convert + pad (outw only) ----------------
__global__ void cvt_pad_kernel(const float* __restrict__ src, __half* __restrict__ dst,
                               int K, int N, int NP, int total2) {
    int idx = blockIdx.x * blockDim.x + threadIdx.x;
    if (idx >= total2) return;
    int np2 = NP >> 1;
    int n = (idx % np2) << 1;
    int k = idx / np2;
    const float* s = src + (size_t)k * N;
    float v0 = (n < N) ? s[n] : 0.f;
    float v1 = (n + 1 < N) ? s[n + 1] : 0.f;
    *reinterpret_cast<__half2*>(dst + (size_t)k * NP + n) = __floats2half2_rn(v0, v1);
}

// ---------------- qkv weights gather, div-free ----------------
// grid (Dd/64, 3*Hh, Ll), block 256: thread -> 16 contiguous e of one d row.
__global__ void __launch_bounds__(256)
tqkv16b_kernel(const float* __restrict__ wq, const float* __restrict__ wk,
               const float* __restrict__ wv, __half* __restrict__ dst) {
    const int l = blockIdx.z;
    const int wy = blockIdx.y;               // 0..35
    const int w = wy / 12, h = wy % 12;      // block-level, cheap
    const int d = blockIdx.x * 64 + (threadIdx.x >> 2);
    const int e0 = (threadIdx.x & 3) << 4;
    const float* src = (w == 0) ? wq : (w == 1) ? wk : wv;
    const float* sp = src + (((size_t)l * Hh + h) * Dd + d) * HD + e0;
    __half* dp = dst + ((size_t)l * Dd + d) * QS + w * Dd + h * HD + e0;
#pragma unroll
    for (int j = 0; j < 4; j++) {
        float4 a = *reinterpret_cast<const float4*>(sp + j * 4);
        *reinterpret_cast<uint2*>(dp + j * 4) = make_uint2(
            h2u(__floats2half2_rn(a.x, a.y)), h2u(__floats2half2_rn(a.z, a.w)));
    }
}

__global__ void bqkv_kernel(const float* __restrict__ bq,
                            const float* __restrict__ bk,
                            const float* __restrict__ bv,
                            float* __restrict__ dst) {
    int idx = blockIdx.x * blockDim.x + threadIdx.x;
    if (idx >= Ll * QS) return;
    int n2 = idx % QS, l = idx / QS;
    int w = n2 / Dd, n = n2 % Dd;
    const float* src = (w == 0) ? bq : (w == 1) ? bk : bv;
    dst[idx] = src[l * Dd + n];
}

// ---------------- layernorm ----------------
__global__ void __launch_bounds__(256)
ln_kernel(const float* __restrict__ in, __half* __restrict__ out,
          const float* __restrict__ g, const float* __restrict__ b) {
    const int warp = threadIdx.x >> 5;
    const int lane = threadIdx.x & 31;
    const int row = blockIdx.x * 8 + warp;
    const float* x = in + (size_t)row * Dd;
    float4 v[6];
    float s = 0.f, s2 = 0.f;
#pragma unroll
    for (int i = 0; i < 6; i++) {
        v[i] = *reinterpret_cast<const float4*>(x + i * 128 + lane * 4);
        s += v[i].x + v[i].y + v[i].z + v[i].w;
        s2 += v[i].x * v[i].x + v[i].y * v[i].y + v[i].z * v[i].z + v[i].w * v[i].w;
    }
#pragma unroll
    for (int off = 16; off > 0; off >>= 1) {
        s += __shfl_xor_sync(0xffffffffu, s, off);
        s2 += __shfl_xor_sync(0xffffffffu, s2, off);
    }
    float mean = s * (1.f / Dd);
    float var = s2 * (1.f / Dd) - mean * mean;
    float rstd = rsqrtf(var + EPS);
    __half* y = out + (size_t)row * Dd;
#pragma unroll
    for (int i = 0; i < 6; i++) {
        float4 gg = *reinterpret_cast<const float4*>(g + i * 128 + lane * 4);
        float4 bb = *reinterpret_cast<const float4*>(b + i * 128 + lane * 4);
        float wx = (v[i].x - mean) * rstd * gg.x + bb.x;
        float wy = (v[i].y - mean) * rstd * gg.y + bb.y;
        float wz = (v[i].z - mean) * rstd * gg.z + bb.z;
        float ww = (v[i].w - mean) * rstd * gg.w + bb.w;
        *reinterpret_cast<__half2*>(y + i * 128 + lane * 4) = __floats2half2_rn(wx, wy);
        *reinterpret_cast<__half2*>(y + i * 128 + lane * 4 + 2) = __floats2half2_rn(wz, ww);
    }
}

constexpr int SAH = 40;
constexpr int NSTG = 5;

// ---------------- hgemm2: 128-thr, 4 warps (2M x 2N), warp tile 64 x BN/2 ----------------
// LSE: accumulate sum(exp(C)) partials per row (logits GEMM only).
template <int BN, bool RELU, bool RES, bool GUARD, bool HOUT, bool DUAL, bool LSE>
__global__ void __launch_bounds__(128, 2)
hgemm2_kernel(int N, int K, int ldb, int ldc,
              const __half* __restrict__ A, const __half* __restrict__ W,
              const float* __restrict__ bias, const float* __restrict__ res,
              void* __restrict__ Cout, __half* __restrict__ C16,
              float* __restrict__ part) {
    constexpr int SBN = BN + 8;
    constexpr int NI = BN / 16;
    constexpr int NJ = NI / 2;
    constexpr int CPB = BN / 8;
    constexpr int ABYTES = 128 * SAH * 2;
    constexpr int BBYTES = 32 * SBN * 2;
    constexpr int STGB = ABYTES + BBYTES;
    extern __shared__ char smem[];

    const int tid = threadIdx.x;
    const int lane = tid & 31;
    const int wid = tid >> 5;
    const int wm = wid & 1;
    const int wn = wid >> 1;
    const int bm = blockIdx.x * 128;
    const int bn = blockIdx.y * BN;
    const uint32_t sbase = smem_u32(smem);

    const __half* Ag = A + (size_t)bm * K;
    const __half* Wg = W + bn;
    const int NT = K >> 5;

    float acc[4][NI][4];
#pragma unroll
    for (int i = 0; i < 4; i++)
#pragma unroll
        for (int j = 0; j < NI; j++)
#pragma unroll
            for (int k = 0; k < 4; k++) acc[i][j][k] = 0.f;

    auto issue = [&](int it) {
        const int kof = it << 5;
        const uint32_t sa = sbase + (it % NSTG) * STGB;
        const uint32_t sb = sa + ABYTES;
#pragma unroll
        for (int i = 0; i < 4; i++) {
            int idx = tid + (i << 7);
            int row = idx >> 2;
            int cc = (idx & 3) << 3;
            cp16(sa + (uint32_t)(row * SAH + cc) * 2, Ag + (size_t)row * K + kof + cc);
        }
#pragma unroll
        for (int i = 0; i < BN / 32; i++) {
            int idx = tid + (i << 7);
            int row = idx / CPB;
            int cc = (idx % CPB) << 3;
            cp16(sb + (uint32_t)(row * SBN + cc) * 2, Wg + (size_t)(kof + row) * ldb + cc);
        }
        CP_COMMIT();
    };

#pragma unroll
    for (int it = 0; it < NSTG - 1; it++) {
        if (it < NT) issue(it);
        else CP_COMMIT();
    }

    const int tA = lane >> 3;
    const int rr = (lane & 7) + ((tA & 1) << 3);
    const int co = (tA >> 1) << 3;

    for (int it = 0; it < NT; it++) {
        cp_wait<NSTG - 2>();
        __syncthreads();
        if (it + NSTG - 1 < NT) issue(it + NSTG - 1);
        else CP_COMMIT();

        const uint32_t sAu = sbase + (it % NSTG) * STGB;
        const uint32_t sBu = sAu + ABYTES;
#pragma unroll
        for (int ks = 0; ks < 2; ks++) {
            const int kb = ks * 16;
            uint32_t a[4][4], b[NJ][4];
#pragma unroll
            for (int mi = 0; mi < 4; mi++)
                LDSM_X4(a[mi], sAu + (uint32_t)((wm * 64 + mi * 16 + rr) * SAH + kb + co) * 2);
#pragma unroll
            for (int nj = 0; nj < NJ; nj++)
                LDSM_X4T(b[nj], sBu + (uint32_t)((kb + rr) * SBN + wn * (BN / 2) + nj * 16 + co) * 2);
#pragma unroll
            for (int mi = 0; mi < 4; mi++)
#pragma unroll
                for (int nj = 0; nj < NJ; nj++) {
                    mma_f16(acc[mi][2 * nj], a[mi], b[nj]);
                    mma_f16(acc[mi][2 * nj + 1], a[mi], b[nj] + 2);
                }
        }
    }

    float* Cf = reinterpret_cast<float*>(Cout);
    __half* Ch = reinterpret_cast<__half*>(Cout);
#pragma unroll
    for (int mi = 0; mi < 4; mi++) {
        const int m0 = bm + wm * 64 + mi * 16 + (lane >> 2);
        float es[2] = {0.f, 0.f};
#pragma unroll
        for (int ni = 0; ni < NI; ni++) {
            const int n0 = bn + wn * (BN / 2) + ni * 8 + ((lane & 3) << 1);
            const float* c = acc[mi][ni];
#pragma unroll
            for (int hf = 0; hf < 2; hf++) {
                const int m = m0 + hf * 8;
                if (HOUT) {
                    float v0 = c[hf * 2 + 0] + bias[n0];
                    float v1 = c[hf * 2 + 1] + bias[n0 + 1];
                    if (RES) {
                        v0 += res[(size_t)m * ldc + n0];
                        v1 += res[(size_t)m * ldc + n0 + 1];
                    }
                    if (RELU) { v0 = fmaxf(v0, 0.f); v1 = fmaxf(v1, 0.f); }
                    *reinterpret_cast<__half2*>(&Ch[(size_t)m * ldc + n0]) =
                        __floats2half2_rn(v0, v1);
                } else if (!GUARD) {
                    float v0 = c[hf * 2 + 0] + bias[n0];
                    float v1 = c[hf * 2 + 1] + bias[n0 + 1];
                    if (RES) {
                        v0 += res[(size_t)m * ldc + n0];
                        v1 += res[(size_t)m * ldc + n0 + 1];
                    }
                    if (RELU) { v0 = fmaxf(v0, 0.f); v1 = fmaxf(v1, 0.f); }
                    Cf[(size_t)m * ldc + n0] = v0;
                    Cf[(size_t)m * ldc + n0 + 1] = v1;
                    if (DUAL)
                        *reinterpret_cast<__half2*>(&C16[(size_t)m * ldc + n0]) =
                            __floats2half2_rn(v0, v1);
                } else {
                    if (n0 < N) {
                        float v = c[hf * 2 + 0] + bias[n0];
                        if (RELU) v = fmaxf(v, 0.f);
                        Cf[(size_t)m * ldc + n0] = v;
                        if (LSE) es[hf] += __expf(v);
                    }
                    if (n0 + 1 < N) {
                        float v = c[hf * 2 + 1] + bias[n0 + 1];
                        if (RELU) v = fmaxf(v, 0.f);
                        Cf[(size_t)m * ldc + n0 + 1] = v;
                        if (LSE) es[hf] += __expf(v);
                    }
                }
            }
        }
        if (LSE) {
#pragma unroll
            for (int hf = 0; hf < 2; hf++) {
                float e = es[hf];
                e += __shfl_xor_sync(0xffffffffu, e, 1);
                e += __shfl_xor_sync(0xffffffffu, e, 2);
                if ((lane & 3) == 0)
                    part[(size_t)(m0 + hf * 8) * NPART + blockIdx.y * 2 + wn] = e;
            }
        }
    }
}

// ---------------- tensor-core flash attention ----------------
constexpr int FST = 72;

__global__ void __launch_bounds__(128)
flashmma_kernel(const __half* __restrict__ QKV, __half* __restrict__ O) {
    const int bh = blockIdx.y;
    const int b = bh / Hh, h = bh % Hh;
    const int t0 = blockIdx.x * 64;
    __shared__ __half Kt[64 * FST];
    __shared__ __half Qs[64 * FST];
    __shared__ __half Vs[64 * FST];
    const int tid = threadIdx.x;
    const int lane = tid & 31;
    const int w = tid >> 5;
    const __half* qg = QKV + (size_t)b * Tt * QS + h * HD;
    const __half* kg = qg + Dd;
    const __half* vg = qg + 2 * Dd;

#pragma unroll
    for (int i = 0; i < 4; i++) {
        int idx = tid + i * 128;
        int r = idx >> 3, cc = (idx & 7) << 3;
        *reinterpret_cast<uint4*>(&Kt[r * FST + cc]) =
            *reinterpret_cast<const uint4*>(&kg[(size_t)(t0 + r) * QS + cc]);
    }
    __syncthreads();

    uint32_t ka[4][4];
    {
        const int tile = lane >> 3;
        const int mrow = w * 16 + (lane & 7) + ((tile & 1) << 3);
        const int eofs = (tile >> 1) << 3;
#pragma unroll
        for (int c = 0; c < 4; c++)
            LDSM_X4(ka[c], smem_u32(&Kt[mrow * FST + c * 16 + eofs]));
    }

    float m0 = -INFINITY, m1 = -INFINITY, l0 = 0.f, l1 = 0.f;
    float o[8][4];
#pragma unroll
    for (int j = 0; j < 8; j++)
#pragma unroll
        for (int k = 0; k < 4; k++) o[j][k] = 0.f;

    for (int s0 = 0; s0 <= t0; s0 += 64) {
#pragma unroll
        for (int i = 0; i < 4; i++) {
            int idx = tid + i * 128;
            int r = idx >> 3, cc = (idx & 7) << 3;
            *reinterpret_cast<uint4*>(&Qs[r * FST + cc]) =
                *reinterpret_cast<const uint4*>(&qg[(size_t)(s0 + r) * QS + cc]);
            *reinterpret_cast<uint4*>(&Vs[r * FST + cc]) =
                *reinterpret_cast<const uint4*>(&vg[(size_t)(s0 + r) * QS + cc]);
        }
        __syncthreads();

        float sacc[8][4];
#pragma unroll
        for (int j = 0; j < 8; j++)
#pragma unroll
            for (int k = 0; k < 4; k++) sacc[j][k] = 0.f;
        {
            const int tile = lane >> 3;
            const int rofs = (lane & 7) + ((tile >> 1) << 3);
            const int eofs = (tile & 1) << 3;
#pragma unroll
            for (int g = 0; g < 4; g++)
#pragma unroll
                for (int c = 0; c < 4; c++) {
                    uint32_t qb[4];
                    LDSM_X4(qb, smem_u32(&Qs[(g * 16 + rofs) * FST + c * 16 + eofs]));
                    mma_f16(sacc[2 * g], ka[c], qb);
                    mma_f16(sacc[2 * g + 1], ka[c], qb + 2);
                }
        }

        if (s0 == t0) {
            const int r0 = w * 16 + (lane >> 2);
            const int cb = (lane & 3) << 1;
#pragma unroll
            for (int j = 0; j < 8; j++) {
                int sb = j * 8 + cb;
                if (sb > r0) sacc[j][0] = -INFINITY;
                if (sb + 1 > r0) sacc[j][1] = -INFINITY;
                if (sb > r0 + 8) sacc[j][2] = -INFINITY;
                if (sb + 1 > r0 + 8) sacc[j][3] = -INFINITY;
            }
        }

        float mx0 = -INFINITY, mx1 = -INFINITY;
#pragma unroll
        for (int j = 0; j < 8; j++) {
            mx0 = fmaxf(mx0, fmaxf(sacc[j][0], sacc[j][1]));
            mx1 = fmaxf(mx1, fmaxf(sacc[j][2], sacc[j][3]));
        }
        mx0 = fmaxf(mx0, __shfl_xor_sync(0xffffffffu, mx0, 1));
        mx0 = fmaxf(mx0, __shfl_xor_sync(0xffffffffu, mx0, 2));
        mx1 = fmaxf(mx1, __shfl_xor_sync(0xffffffffu, mx1, 1));
        mx1 = fmaxf(mx1, __shfl_xor_sync(0xffffffffu, mx1, 2));
        float mn0 = fmaxf(m0, mx0), mn1 = fmaxf(m1, mx1);
        float sc0 = __expf(m0 - mn0), sc1 = __expf(m1 - mn1);
        float su0 = 0.f, su1 = 0.f;
#pragma unroll
        for (int j = 0; j < 8; j++) {
            sacc[j][0] = __expf(sacc[j][0] - mn0);
            sacc[j][1] = __expf(sacc[j][1] - mn0);
            sacc[j][2] = __expf(sacc[j][2] - mn1);
            sacc[j][3] = __expf(sacc[j][3] - mn1);
            su0 += sacc[j][0] + sacc[j][1];
            su1 += sacc[j][2] + sacc[j][3];
        }
        su0 += __shfl_xor_sync(0xffffffffu, su0, 1);
        su0 += __shfl_xor_sync(0xffffffffu, su0, 2);
        su1 += __shfl_xor_sync(0xffffffffu, su1, 1);
        su1 += __shfl_xor_sync(0xffffffffu, su1, 2);
        l0 = l0 * sc0 + su0;
        l1 = l1 * sc1 + su1;
        m0 = mn0; m1 = mn1;
#pragma unroll
        for (int j = 0; j < 8; j++) {
            o[j][0] *= sc0; o[j][1] *= sc0;
            o[j][2] *= sc1; o[j][3] *= sc1;
        }

        {
            const int tile = lane >> 3;
            const int rofs = (lane & 7) + ((tile & 1) << 3);
            const int eofs = (tile >> 1) << 3;
#pragma unroll
            for (int c = 0; c < 4; c++) {
                uint32_t ap[4];
                ap[0] = h2u(__floats2half2_rn(sacc[2 * c][0], sacc[2 * c][1]));
                ap[1] = h2u(__floats2half2_rn(sacc[2 * c][2], sacc[2 * c][3]));
                ap[2] = h2u(__floats2half2_rn(sacc[2 * c + 1][0], sacc[2 * c + 1][1]));
                ap[3] = h2u(__floats2half2_rn(sacc[2 * c + 1][2], sacc[2 * c + 1][3]));
#pragma unroll
                for (int g = 0; g < 4; g++) {
                    uint32_t vb[4];
                    LDSM_X4T(vb, smem_u32(&Vs[(c * 16 + rofs) * FST + g * 16 + eofs]));
                    mma_f16(o[2 * g], ap, vb);
                    mma_f16(o[2 * g + 1], ap, vb + 2);
                }
            }
        }
        __syncthreads();
    }

    const float inv0 = 1.f / l0, inv1 = 1.f / l1;
    const int trow = t0 + w * 16 + (lane >> 2);
    const int cb = (lane & 3) << 1;
    __half* ob = O + (size_t)b * Tt * Dd + h * HD;
#pragma unroll
    for (int j = 0; j < 8; j++) {
        *reinterpret_cast<__half2*>(&ob[(size_t)trow * Dd + j * 8 + cb]) =
            __floats2half2_rn(o[j][0] * inv0, o[j][1] * inv0);
        *reinterpret_cast<__half2*>(&ob[(size_t)(trow + 8) * Dd + j * 8 + cb]) =
            __floats2half2_rn(o[j][2] * inv1, o[j][3] * inv1);
    }
}

// ---------------- nll from lse partials ----------------
__global__ void __launch_bounds__(256)
nll_combine_kernel(const float* __restrict__ part, const float* __restrict__ logits,
                   const int* __restrict__ target, float* __restrict__ nll) {
    int row = blockIdx.x;
    const float* pr = part + (size_t)row * NPART;
    int tid = threadIdx.x;
    float s = 0.f;
    for (int p = tid; p < NPART; p += 256) s += pr[p];
    __shared__ float red[256];
    red[tid] = s;
    __syncthreads();
    for (int off = 128; off > 0; off >>= 1) {
        if (tid < off) red[tid] += red[tid + off];
        __syncthreads();
    }
    if (tid == 0)
        nll[row] = logf(red[0]) - logits[(size_t)row * Vv + target[row]];
}

__global__ void loss_reduce_kernel(const float* __restrict__ nll, float* __restrict__ out) {
    __shared__ float red[256];
    int tid = threadIdx.x;
    float s = 0.f;
    for (int i = tid; i < BT; i += 256) s += nll[i];
    red[tid] = s; __syncthreads();
    for (int off = 128; off > 0; off >>= 1) {
        if (tid < off) red[tid] += red[tid + off];
        __syncthreads();
    }
    if (tid == 0) out[0] = red[0] * (1.f / BT);
}

// ---------------- host driver ----------------
extern "C" void kernel_launch(void* const* d_in, const int* in_sizes, int n_in,
                              void* d_out, int out_size) {
    const int* x      = (const int*)d_in[0];
    const int* target = (const int*)d_in[1];
    const float* tok  = (const float*)d_in[2];
    const float* pos  = (const float*)d_in[3];
    const float* ipw  = (const float*)d_in[4];
    const float* ipb  = (const float*)d_in[5];
    const float* wk   = (const float*)d_in[6];
    const float* bk   = (const float*)d_in[7];
    const float* wq   = (const float*)d_in[8];
    const float* bq   = (const float*)d_in[9];
    const float* wv   = (const float*)d_in[10];
    const float* bv   = (const float*)d_in[11];
    const float* opw  = (const float*)d_in[12];
    const float* opb  = (const float*)d_in[13];
    const float* w1   = (const float*)d_in[14];
    const float* b1   = (const float*)d_in[15];
    const float* w2   = (const float*)d_in[16];
    const float* b2   = (const float*)d_in[17];
    const float* lnag = (const float*)d_in[18];
    const float* lnab = (const float*)d_in[19];
    const float* lnfg = (const float*)d_in[20];
    const float* lnfb = (const float*)d_in[21];
    const float* outw = (const float*)d_in[22];
    const float* outb = (const float*)d_in[23];
    float* out = (float*)d_out;

    float *p_x, *p_bqkv, *p_part, *p_nll, *p_lfb;
    __half *p_ln16, *p_h16, *p_qkv16, *p_attn16, *p_ff16, *p_x16;
    __half *p_wT, *p_ipw, *p_opw, *p_w1, *p_w2, *p_wpad;
    cudaGetSymbolAddress((void**)&p_x, g_x);
    cudaGetSymbolAddress((void**)&p_ln16, g_ln16);
    cudaGetSymbolAddress((void**)&p_h16, g_h16);
    cudaGetSymbolAddress((void**)&p_qkv16, g_qkv16);
    cudaGetSymbolAddress((void**)&p_attn16, g_attn16);
    cudaGetSymbolAddress((void**)&p_ff16, g_ff16);
    cudaGetSymbolAddress((void**)&p_x16, g_x16);
    cudaGetSymbolAddress((void**)&p_wT, g_wT16);
    cudaGetSymbolAddress((void**)&p_ipw, g_ipw16);
    cudaGetSymbolAddress((void**)&p_opw, g_opw16);
    cudaGetSymbolAddress((void**)&p_w1, g_w116);
    cudaGetSymbolAddress((void**)&p_w2, g_w216);
    cudaGetSymbolAddress((void**)&p_wpad, g_wpad16);
    cudaGetSymbolAddress((void**)&p_bqkv, g_bqkv);
    cudaGetSymbolAddress((void**)&p_part, g_part);
    cudaGetSymbolAddress((void**)&p_nll, g_nll);
    cudaGetSymbolAddress((void**)&p_lfb, g_logits_fb);

    constexpr int SM64 = (128 * SAH * 2 + 32 * 72 * 2) * NSTG;     // 74240
    constexpr int SM128 = (128 * SAH * 2 + 32 * 136 * 2) * NSTG;   // 94720
    cudaFuncSetAttribute(hgemm2_kernel<64, false, false, false, true, false, false>,
                         cudaFuncAttributeMaxDynamicSharedMemorySize, SM64);
    cudaFuncSetAttribute(hgemm2_kernel<64, false, true, false, false, false, false>,
                         cudaFuncAttributeMaxDynamicSharedMemorySize, SM64);
    cudaFuncSetAttribute(hgemm2_kernel<64, false, true, false, false, true, false>,
                         cudaFuncAttributeMaxDynamicSharedMemorySize, SM64);
    cudaFuncSetAttribute(hgemm2_kernel<128, false, false, false, true, false, false>,
                         cudaFuncAttributeMaxDynamicSharedMemorySize, SM128);
    cudaFuncSetAttribute(hgemm2_kernel<128, true, false, false, true, false, false>,
                         cudaFuncAttributeMaxDynamicSharedMemorySize, SM128);
    cudaFuncSetAttribute(hgemm2_kernel<128, false, false, true, false, false, true>,
                         cudaFuncAttributeMaxDynamicSharedMemorySize, SM128);

    const size_t BTV = (size_t)BT * Vv;
    float* logits_dst = ((size_t)out_size >= BTV) ? out : p_lfb;

    embed_kernel<<<BT, 256>>>(x, tok, pos, p_x);
    {
        int total = 2 * WSZ1 + 2 * WSZ2;
        cvt_all_kernel<<<(total + 255) / 256, 256>>>(ipw, p_ipw, opw, p_opw,
                                                     w1, p_w1, w2, p_w2);
        int t2v = Dd * VP / 2;
        cvt_pad_kernel<<<(t2v + 255) / 256, 256>>>(outw, p_wpad, Dd, Vv, VP, t2v);
    }
    tqkv16b_kernel<<<dim3(Dd / 64, 3 * Hh, Ll), 256>>>(wq, wk, wv, p_wT);
    bqkv_kernel<<<(Ll * QS + 255) / 256, 256>>>(bq, bk, bv, p_bqkv);

    dim3 gD(16, Dd / 64);       // (16,12)
    dim3 gQ(16, QS / 128);      // (16,18)
    dim3 gF(16, FF / 128);      // (16,24)
    dim3 gV(16, VP / 128);      // (16,394)

    for (int l = 0; l < Ll; l++) {
        ln_kernel<<<BT / 8, 256>>>(p_x, p_ln16, lnag + (size_t)l * Dd, lnab + (size_t)l * Dd);
        hgemm2_kernel<64, false, false, false, true, false, false><<<gD, 128, SM64>>>(
            Dd, Dd, Dd, Dd, p_ln16, p_ipw + (size_t)l * Dd * Dd, ipb + (size_t)l * Dd,
            nullptr, p_h16, nullptr, nullptr);

        hgemm2_kernel<128, false, false, false, true, false, false><<<gQ, 128, SM128>>>(
            QS, Dd, QS, QS, p_h16, p_wT + (size_t)l * Dd * QS, p_bqkv + (size_t)l * QS,
            nullptr, p_qkv16, nullptr, nullptr);

        flashmma_kernel<<<dim3(Tt / 64, Bb * Hh), 128>>>(p_qkv16, p_attn16);

        hgemm2_kernel<64, false, true, false, false, false, false><<<gD, 128, SM64>>>(
            Dd, Dd, Dd, Dd, p_attn16, p_opw + (size_t)l * Dd * Dd, opb + (size_t)l * Dd,
            p_x, p_x, nullptr, nullptr);

        ln_kernel<<<BT / 8, 256>>>(p_x, p_ln16, lnfg + (size_t)l * Dd, lnfb + (size_t)l * Dd);
        hgemm2_kernel<128, true, false, false, true, false, false><<<gF, 128, SM128>>>(
            FF, Dd, FF, FF, p_ln16, p_w1 + (size_t)l * Dd * FF, b1 + (size_t)l * FF,
            nullptr, p_ff16, nullptr, nullptr);
        if (l == Ll - 1) {
            hgemm2_kernel<64, false, true, false, false, true, false><<<gD, 128, SM64>>>(
                Dd, FF, Dd, Dd, p_ff16, p_w2 + (size_t)l * FF * Dd, b2 + (size_t)l * Dd,
                p_x, p_x, p_x16, nullptr);
        } else {
            hgemm2_kernel<64, false, true, false, false, false, false><<<gD, 128, SM64>>>(
                Dd, FF, Dd, Dd, p_ff16, p_w2 + (size_t)l * FF * Dd, b2 + (size_t)l * Dd,
                p_x, p_x, nullptr, nullptr);
        }
    }

    hgemm2_kernel<128, false, false, true, false, false, true><<<gV, 128, SM128>>>(
        Vv, Dd, VP, Vv, p_x16, p_wpad, outb, nullptr, logits_dst, nullptr, p_part);

    nll_combine_kernel<<<BT, 256>>>(p_part, logits_dst, target, p_nll);
    if ((size_t)out_size > BTV) {
        loss_reduce_kernel<<<1, 256>>>(p_nll, out + BTV);
    } else if (out_size == 1) {
        loss_reduce_kernel<<<1, 256>>>(p_nll, out);
    }
}

// round 17
// speedup vs baseline: 1.0116x; 1.0116x over previous
#include <cuda_runtime.h>
#include <cuda_fp16.h>
#include <math.h>
#include <stdint.h>
#include <string.h>

// Problem constants
constexpr int Bb = 4;
constexpr int Tt = 512;
constexpr int BT = Bb * Tt;          // 2048
constexpr int Dd = 768;
constexpr int Hh = 12;
constexpr int HD = 64;
constexpr int Ll = 6;
constexpr int Vv = 50257;
constexpr int VP = 50432;            // padded vocab cols (mult of 128)
constexpr int FF = 4 * Dd;           // 3072
constexpr int QS = 3 * Dd;           // 2304
constexpr float EPS = 1e-5f;

// ---------------- static scratch ----------------
__device__ float  g_x[BT * Dd];
__device__ __half g_ln16[BT * Dd];
__device__ __half g_h16[BT * Dd];
__device__ __half g_qkv16[(size_t)BT * QS];
__device__ __half g_attn16[BT * Dd];
__device__ __half g_ff16[(size_t)BT * FF];
__device__ __half g_x16[BT * Dd];
__device__ __half g_wT16[(size_t)Ll * Dd * QS];
__device__ __half g_ipw16[(size_t)Ll * Dd * Dd];
__device__ __half g_opw16[(size_t)Ll * Dd * Dd];
__device__ __half g_w116[(size_t)Ll * Dd * FF];
__device__ __half g_w216[(size_t)Ll * FF * Dd];
__device__ __half g_wpad16[(size_t)Dd * VP];
__device__ float  g_bqkv[Ll * QS];
__device__ float  g_nll[BT];
__device__ float  g_logits_fb[(size_t)BT * Vv];

// ---------------- PTX helpers ----------------
__device__ __forceinline__ uint32_t smem_u32(const void* p) {
    uint32_t a;
    asm("{ .reg .u64 t; cvta.to.shared.u64 t, %1; cvt.u32.u64 %0, t; }"
        : "=r"(a) : "l"(p));
    return a;
}
__device__ __forceinline__ uint32_t h2u(__half2 h) {
    uint32_t u;
    memcpy(&u, &h, 4);
    return u;
}
__device__ __forceinline__ void cp16(uint32_t s, const void* g) {
    asm volatile("cp.async.cg.shared.global [%0], [%1], 16;" :: "r"(s), "l"(g));
}
#define CP_COMMIT() asm volatile("cp.async.commit_group;" ::: "memory")
template <int N>
__device__ __forceinline__ void cp_wait() {
    asm volatile("cp.async.wait_group %0;" :: "n"(N) : "memory");
}
__device__ __forceinline__ void mma_f16(float* c, const uint32_t* a, const uint32_t* b) {
    asm volatile(
        "mma.sync.aligned.m16n8k16.row.col.f32.f16.f16.f32 "
        "{%0,%1,%2,%3}, {%4,%5,%6,%7}, {%8,%9}, {%0,%1,%2,%3};"
        : "+f"(c[0]), "+f"(c[1]), "+f"(c[2]), "+f"(c[3])
        : "r"(a[0]), "r"(a[1]), "r"(a[2]), "r"(a[3]), "r"(b[0]), "r"(b[1]));
}
#define LDSM_X4(r, addr) \
    asm volatile("ldmatrix.sync.aligned.m8n8.x4.shared.b16 {%0,%1,%2,%3}, [%4];" \
        : "=r"((r)[0]), "=r"((r)[1]), "=r"((r)[2]), "=r"((r)[3]) : "r"(addr))
#define LDSM_X4T(r, addr) \
    asm volatile("ldmatrix.sync.aligned.m8n8.x4.trans.shared.b16 {%0,%1,%2,%3}, [%4];" \
        : "=r"((r)[0]), "=r"((r)[1]), "=r"((r)[2]), "=r"((r)[3]) : "r"(addr))

// ---------------- embedding ----------------
__global__ void embed_kernel(const int* __restrict__ x,
                             const float* __restrict__ tok,
                             const float* __restrict__ pos,
                             float* __restrict__ out) {
    int row = blockIdx.x;
    int id = x[row];
    int t = row % Tt;
    const float* tp = tok + (size_t)id * Dd;
    const float* pp = pos + (size_t)t * Dd;
    float* op = out + (size_t)row * Dd;
    for (int d = threadIdx.x; d < Dd; d += blockDim.x)
        op[d] = tp[d] + pp[d];
}

// ---------------- all-weights convert: 4 contiguous regions, one launch ----------------
constexpr int WSZ1 = Ll * Dd * Dd / 16;
constexpr int WSZ2 = Ll * Dd * FF / 16;
__global__ void cvt_all_kernel(const float* __restrict__ s0, __half* __restrict__ d0,
                               const float* __restrict__ s1, __half* __restrict__ d1,
                               const float* __restrict__ s2, __half* __restrict__ d2,
                               const float* __restrict__ s3, __half* __restrict__ d3) {
    int i = blockIdx.x * blockDim.x + threadIdx.x;
    const float* src;
    __half* dst;
    int r;
    if (i < WSZ1) { src = s0; dst = d0; r = i; }
    else if (i < 2 * WSZ1) { src = s1; dst = d1; r = i - WSZ1; }
    else if (i < 2 * WSZ1 + WSZ2) { src = s2; dst = d2; r = i - 2 * WSZ1; }
    else if (i < 2 * WSZ1 + 2 * WSZ2) { src = s3; dst = d3; r = i - 2 * WSZ1 - WSZ2; }
    else return;
#pragma unroll
    for (int j = 0; j < 4; j++) {
        float4 a = *reinterpret_cast<const float4*>(src + (size_t)r * 16 + j * 4);
        __half2 h0 = __floats2half2_rn(a.x, a.y);
        __half2 h1 = __floats2half2_rn(a.z, a.w);
        *reinterpret_cast<uint2*>(dst + (size_t)r * 16 + j * 4) =
            make_uint2(h2u(h0), h2u(h1));
    }
}

// ---------------- convert + pad (outw only) ----------------
__global__ void cvt_pad_kernel(const float* __restrict__ src, __half* __restrict__ dst,
                               int K, int N, int NP, int total2) {
    int idx = blockIdx.x * blockDim.x + threadIdx.x;
    if (idx >= total2) return;
    int np2 = NP >> 1;
    int n = (idx % np2) << 1;
    int k = idx / np2;
    const float* s = src + (size_t)k * N;
    float v0 = (n < N) ? s[n] : 0.f;
    float v1 = (n + 1 < N) ? s[n + 1] : 0.f;
    *reinterpret_cast<__half2*>(dst + (size_t)k * NP + n) = __floats2half2_rn(v0, v1);
}

// ---------------- qkv weights gather, div-free ----------------
__global__ void __launch_bounds__(256)
tqkv16b_kernel(const float* __restrict__ wq, const float* __restrict__ wk,
               const float* __restrict__ wv, __half* __restrict__ dst) {
    const int l = blockIdx.z;
    const int wy = blockIdx.y;               // 0..35
    const int w = wy / 12, h = wy % 12;
    const int d = blockIdx.x * 64 + (threadIdx.x >> 2);
    const int e0 = (threadIdx.x & 3) << 4;
    const float* src = (w == 0) ? wq : (w == 1) ? wk : wv;
    const float* sp = src + (((size_t)l * Hh + h) * Dd + d) * HD + e0;
    __half* dp = dst + ((size_t)l * Dd + d) * QS + w * Dd + h * HD + e0;
#pragma unroll
    for (int j = 0; j < 4; j++) {
        float4 a = *reinterpret_cast<const float4*>(sp + j * 4);
        *reinterpret_cast<uint2*>(dp + j * 4) = make_uint2(
            h2u(__floats2half2_rn(a.x, a.y)), h2u(__floats2half2_rn(a.z, a.w)));
    }
}

__global__ void bqkv_kernel(const float* __restrict__ bq,
                            const float* __restrict__ bk,
                            const float* __restrict__ bv,
                            float* __restrict__ dst) {
    int idx = blockIdx.x * blockDim.x + threadIdx.x;
    if (idx >= Ll * QS) return;
    int n2 = idx % QS, l = idx / QS;
    int w = n2 / Dd, n = n2 % Dd;
    const float* src = (w == 0) ? bq : (w == 1) ? bk : bv;
    dst[idx] = src[l * Dd + n];
}

// ---------------- layernorm ----------------
__global__ void __launch_bounds__(256)
ln_kernel(const float* __restrict__ in, __half* __restrict__ out,
          const float* __restrict__ g, const float* __restrict__ b) {
    const int warp = threadIdx.x >> 5;
    const int lane = threadIdx.x & 31;
    const int row = blockIdx.x * 8 + warp;
    const float* x = in + (size_t)row * Dd;
    float4 v[6];
    float s = 0.f, s2 = 0.f;
#pragma unroll
    for (int i = 0; i < 6; i++) {
        v[i] = *reinterpret_cast<const float4*>(x + i * 128 + lane * 4);
        s += v[i].x + v[i].y + v[i].z + v[i].w;
        s2 += v[i].x * v[i].x + v[i].y * v[i].y + v[i].z * v[i].z + v[i].w * v[i].w;
    }
#pragma unroll
    for (int off = 16; off > 0; off >>= 1) {
        s += __shfl_xor_sync(0xffffffffu, s, off);
        s2 += __shfl_xor_sync(0xffffffffu, s2, off);
    }
    float mean = s * (1.f / Dd);
    float var = s2 * (1.f / Dd) - mean * mean;
    float rstd = rsqrtf(var + EPS);
    __half* y = out + (size_t)row * Dd;
#pragma unroll
    for (int i = 0; i < 6; i++) {
        float4 gg = *reinterpret_cast<const float4*>(g + i * 128 + lane * 4);
        float4 bb = *reinterpret_cast<const float4*>(b + i * 128 + lane * 4);
        float wx = (v[i].x - mean) * rstd * gg.x + bb.x;
        float wy = (v[i].y - mean) * rstd * gg.y + bb.y;
        float wz = (v[i].z - mean) * rstd * gg.z + bb.z;
        float ww = (v[i].w - mean) * rstd * gg.w + bb.w;
        *reinterpret_cast<__half2*>(y + i * 128 + lane * 4) = __floats2half2_rn(wx, wy);
        *reinterpret_cast<__half2*>(y + i * 128 + lane * 4 + 2) = __floats2half2_rn(wz, ww);
    }
}

constexpr int SAH = 40;
constexpr int NSTG = 5;

// ---------------- hgemm2: 128-thr, 4 warps (2M x 2N), warp tile 64 x BN/2 ----------------
template <int BN, bool RELU, bool RES, bool GUARD, bool HOUT, bool DUAL>
__global__ void __launch_bounds__(128, 2)
hgemm2_kernel(int N, int K, int ldb, int ldc,
              const __half* __restrict__ A, const __half* __restrict__ W,
              const float* __restrict__ bias, const float* __restrict__ res,
              void* __restrict__ Cout, __half* __restrict__ C16) {
    constexpr int SBN = BN + 8;
    constexpr int NI = BN / 16;
    constexpr int NJ = NI / 2;
    constexpr int CPB = BN / 8;
    constexpr int ABYTES = 128 * SAH * 2;
    constexpr int BBYTES = 32 * SBN * 2;
    constexpr int STGB = ABYTES + BBYTES;
    extern __shared__ char smem[];

    const int tid = threadIdx.x;
    const int lane = tid & 31;
    const int wid = tid >> 5;
    const int wm = wid & 1;
    const int wn = wid >> 1;
    const int bm = blockIdx.x * 128;
    const int bn = blockIdx.y * BN;
    const uint32_t sbase = smem_u32(smem);

    const __half* Ag = A + (size_t)bm * K;
    const __half* Wg = W + bn;
    const int NT = K >> 5;

    float acc[4][NI][4];
#pragma unroll
    for (int i = 0; i < 4; i++)
#pragma unroll
        for (int j = 0; j < NI; j++)
#pragma unroll
            for (int k = 0; k < 4; k++) acc[i][j][k] = 0.f;

    auto issue = [&](int it) {
        const int kof = it << 5;
        const uint32_t sa = sbase + (it % NSTG) * STGB;
        const uint32_t sb = sa + ABYTES;
#pragma unroll
        for (int i = 0; i < 4; i++) {
            int idx = tid + (i << 7);
            int row = idx >> 2;
            int cc = (idx & 3) << 3;
            cp16(sa + (uint32_t)(row * SAH + cc) * 2, Ag + (size_t)row * K + kof + cc);
        }
#pragma unroll
        for (int i = 0; i < BN / 32; i++) {
            int idx = tid + (i << 7);
            int row = idx / CPB;
            int cc = (idx % CPB) << 3;
            cp16(sb + (uint32_t)(row * SBN + cc) * 2, Wg + (size_t)(kof + row) * ldb + cc);
        }
        CP_COMMIT();
    };

#pragma unroll
    for (int it = 0; it < NSTG - 1; it++) {
        if (it < NT) issue(it);
        else CP_COMMIT();
    }

    const int tA = lane >> 3;
    const int rr = (lane & 7) + ((tA & 1) << 3);
    const int co = (tA >> 1) << 3;

    for (int it = 0; it < NT; it++) {
        cp_wait<NSTG - 2>();
        __syncthreads();
        if (it + NSTG - 1 < NT) issue(it + NSTG - 1);
        else CP_COMMIT();

        const uint32_t sAu = sbase + (it % NSTG) * STGB;
        const uint32_t sBu = sAu + ABYTES;
#pragma unroll
        for (int ks = 0; ks < 2; ks++) {
            const int kb = ks * 16;
            uint32_t a[4][4], b[NJ][4];
#pragma unroll
            for (int mi = 0; mi < 4; mi++)
                LDSM_X4(a[mi], sAu + (uint32_t)((wm * 64 + mi * 16 + rr) * SAH + kb + co) * 2);
#pragma unroll
            for (int nj = 0; nj < NJ; nj++)
                LDSM_X4T(b[nj], sBu + (uint32_t)((kb + rr) * SBN + wn * (BN / 2) + nj * 16 + co) * 2);
#pragma unroll
            for (int mi = 0; mi < 4; mi++)
#pragma unroll
                for (int nj = 0; nj < NJ; nj++) {
                    mma_f16(acc[mi][2 * nj], a[mi], b[nj]);
                    mma_f16(acc[mi][2 * nj + 1], a[mi], b[nj] + 2);
                }
        }
    }

    float* Cf = reinterpret_cast<float*>(Cout);
    __half* Ch = reinterpret_cast<__half*>(Cout);
#pragma unroll
    for (int mi = 0; mi < 4; mi++) {
        const int m0 = bm + wm * 64 + mi * 16 + (lane >> 2);
#pragma unroll
        for (int ni = 0; ni < NI; ni++) {
            const int n0 = bn + wn * (BN / 2) + ni * 8 + ((lane & 3) << 1);
            const float* c = acc[mi][ni];
#pragma unroll
            for (int hf = 0; hf < 2; hf++) {
                const int m = m0 + hf * 8;
                if (HOUT) {
                    float v0 = c[hf * 2 + 0] + bias[n0];
                    float v1 = c[hf * 2 + 1] + bias[n0 + 1];
                    if (RES) {
                        v0 += res[(size_t)m * ldc + n0];
                        v1 += res[(size_t)m * ldc + n0 + 1];
                    }
                    if (RELU) { v0 = fmaxf(v0, 0.f); v1 = fmaxf(v1, 0.f); }
                    *reinterpret_cast<__half2*>(&Ch[(size_t)m * ldc + n0]) =
                        __floats2half2_rn(v0, v1);
                } else if (!GUARD) {
                    float v0 = c[hf * 2 + 0] + bias[n0];
                    float v1 = c[hf * 2 + 1] + bias[n0 + 1];
                    if (RES) {
                        v0 += res[(size_t)m * ldc + n0];
                        v1 += res[(size_t)m * ldc + n0 + 1];
                    }
                    if (RELU) { v0 = fmaxf(v0, 0.f); v1 = fmaxf(v1, 0.f); }
                    Cf[(size_t)m * ldc + n0] = v0;
                    Cf[(size_t)m * ldc + n0 + 1] = v1;
                    if (DUAL)
                        *reinterpret_cast<__half2*>(&C16[(size_t)m * ldc + n0]) =
                            __floats2half2_rn(v0, v1);
                } else {
                    if (n0 < N) {
                        float v = c[hf * 2 + 0] + bias[n0];
                        if (RELU) v = fmaxf(v, 0.f);
                        Cf[(size_t)m * ldc + n0] = v;
                    }
                    if (n0 + 1 < N) {
                        float v = c[hf * 2 + 1] + bias[n0 + 1];
                        if (RELU) v = fmaxf(v, 0.f);
                        Cf[(size_t)m * ldc + n0 + 1] = v;
                    }
                }
            }
        }
    }
}

// ---------------- tensor-core flash attention ----------------
constexpr int FST = 72;

__global__ void __launch_bounds__(128)
flashmma_kernel(const __half* __restrict__ QKV, __half* __restrict__ O) {
    const int bh = blockIdx.y;
    const int b = bh / Hh, h = bh % Hh;
    const int t0 = blockIdx.x * 64;
    __shared__ __half Kt[64 * FST];
    __shared__ __half Qs[64 * FST];
    __shared__ __half Vs[64 * FST];
    const int tid = threadIdx.x;
    const int lane = tid & 31;
    const int w = tid >> 5;
    const __half* qg = QKV + (size_t)b * Tt * QS + h * HD;
    const __half* kg = qg + Dd;
    const __half* vg = qg + 2 * Dd;

#pragma unroll
    for (int i = 0; i < 4; i++) {
        int idx = tid + i * 128;
        int r = idx >> 3, cc = (idx & 7) << 3;
        *reinterpret_cast<uint4*>(&Kt[r * FST + cc]) =
            *reinterpret_cast<const uint4*>(&kg[(size_t)(t0 + r) * QS + cc]);
    }
    __syncthreads();

    uint32_t ka[4][4];
    {
        const int tile = lane >> 3;
        const int mrow = w * 16 + (lane & 7) + ((tile & 1) << 3);
        const int eofs = (tile >> 1) << 3;
#pragma unroll
        for (int c = 0; c < 4; c++)
            LDSM_X4(ka[c], smem_u32(&Kt[mrow * FST + c * 16 + eofs]));
    }

    float m0 = -INFINITY, m1 = -INFINITY, l0 = 0.f, l1 = 0.f;
    float o[8][4];
#pragma unroll
    for (int j = 0; j < 8; j++)
#pragma unroll
        for (int k = 0; k < 4; k++) o[j][k] = 0.f;

    for (int s0 = 0; s0 <= t0; s0 += 64) {
#pragma unroll
        for (int i = 0; i < 4; i++) {
            int idx = tid + i * 128;
            int r = idx >> 3, cc = (idx & 7) << 3;
            *reinterpret_cast<uint4*>(&Qs[r * FST + cc]) =
                *reinterpret_cast<const uint4*>(&qg[(size_t)(s0 + r) * QS + cc]);
            *reinterpret_cast<uint4*>(&Vs[r * FST + cc]) =
                *reinterpret_cast<const uint4*>(&vg[(size_t)(s0 + r) * QS + cc]);
        }
        __syncthreads();

        float sacc[8][4];
#pragma unroll
        for (int j = 0; j < 8; j++)
#pragma unroll
            for (int k = 0; k < 4; k++) sacc[j][k] = 0.f;
        {
            const int tile = lane >> 3;
            const int rofs = (lane & 7) + ((tile >> 1) << 3);
            const int eofs = (tile & 1) << 3;
#pragma unroll
            for (int g = 0; g < 4; g++)
#pragma unroll
                for (int c = 0; c < 4; c++) {
                    uint32_t qb[4];
                    LDSM_X4(qb, smem_u32(&Qs[(g * 16 + rofs) * FST + c * 16 + eofs]));
                    mma_f16(sacc[2 * g], ka[c], qb);
                    mma_f16(sacc[2 * g + 1], ka[c], qb + 2);
                }
        }

        if (s0 == t0) {
            const int r0 = w * 16 + (lane >> 2);
            const int cb = (lane & 3) << 1;
#pragma unroll
            for (int j = 0; j < 8; j++) {
                int sb = j * 8 + cb;
                if (sb > r0) sacc[j][0] = -INFINITY;
                if (sb + 1 > r0) sacc[j][1] = -INFINITY;
                if (sb > r0 + 8) sacc[j][2] = -INFINITY;
                if (sb + 1 > r0 + 8) sacc[j][3] = -INFINITY;
            }
        }

        float mx0 = -INFINITY, mx1 = -INFINITY;
#pragma unroll
        for (int j = 0; j < 8; j++) {
            mx0 = fmaxf(mx0, fmaxf(sacc[j][0], sacc[j][1]));
            mx1 = fmaxf(mx1, fmaxf(sacc[j][2], sacc[j][3]));
        }
        mx0 = fmaxf(mx0, __shfl_xor_sync(0xffffffffu, mx0, 1));
        mx0 = fmaxf(mx0, __shfl_xor_sync(0xffffffffu, mx0, 2));
        mx1 = fmaxf(mx1, __shfl_xor_sync(0xffffffffu, mx1, 1));
        mx1 = fmaxf(mx1, __shfl_xor_sync(0xffffffffu, mx1, 2));
        float mn0 = fmaxf(m0, mx0), mn1 = fmaxf(m1, mx1);
        float sc0 = __expf(m0 - mn0), sc1 = __expf(m1 - mn1);
        float su0 = 0.f, su1 = 0.f;
#pragma unroll
        for (int j = 0; j < 8; j++) {
            sacc[j][0] = __expf(sacc[j][0] - mn0);
            sacc[j][1] = __expf(sacc[j][1] - mn0);
            sacc[j][2] = __expf(sacc[j][2] - mn1);
            sacc[j][3] = __expf(sacc[j][3] - mn1);
            su0 += sacc[j][0] + sacc[j][1];
            su1 += sacc[j][2] + sacc[j][3];
        }
        su0 += __shfl_xor_sync(0xffffffffu, su0, 1);
        su0 += __shfl_xor_sync(0xffffffffu, su0, 2);
        su1 += __shfl_xor_sync(0xffffffffu, su1, 1);
        su1 += __shfl_xor_sync(0xffffffffu, su1, 2);
        l0 = l0 * sc0 + su0;
        l1 = l1 * sc1 + su1;
        m0 = mn0; m1 = mn1;
#pragma unroll
        for (int j = 0; j < 8; j++) {
            o[j][0] *= sc0; o[j][1] *= sc0;
            o[j][2] *= sc1; o[j][3] *= sc1;
        }

        {
            const int tile = lane >> 3;
            const int rofs = (lane & 7) + ((tile & 1) << 3);
            const int eofs = (tile >> 1) << 3;
#pragma unroll
            for (int c = 0; c < 4; c++) {
                uint32_t ap[4];
                ap[0] = h2u(__floats2half2_rn(sacc[2 * c][0], sacc[2 * c][1]));
                ap[1] = h2u(__floats2half2_rn(sacc[2 * c][2], sacc[2 * c][3]));
                ap[2] = h2u(__floats2half2_rn(sacc[2 * c + 1][0], sacc[2 * c + 1][1]));
                ap[3] = h2u(__floats2half2_rn(sacc[2 * c + 1][2], sacc[2 * c + 1][3]));
#pragma unroll
                for (int g = 0; g < 4; g++) {
                    uint32_t vb[4];
                    LDSM_X4T(vb, smem_u32(&Vs[(c * 16 + rofs) * FST + g * 16 + eofs]));
                    mma_f16(o[2 * g], ap, vb);
                    mma_f16(o[2 * g + 1], ap, vb + 2);
                }
            }
        }
        __syncthreads();
    }

    const float inv0 = 1.f / l0, inv1 = 1.f / l1;
    const int trow = t0 + w * 16 + (lane >> 2);
    const int cb = (lane & 3) << 1;
    __half* ob = O + (size_t)b * Tt * Dd + h * HD;
#pragma unroll
    for (int j = 0; j < 8; j++) {
        *reinterpret_cast<__half2*>(&ob[(size_t)trow * Dd + j * 8 + cb]) =
            __floats2half2_rn(o[j][0] * inv0, o[j][1] * inv0);
        *reinterpret_cast<__half2*>(&ob[(size_t)(trow + 8) * Dd + j * 8 + cb]) =
            __floats2half2_rn(o[j][2] * inv1, o[j][3] * inv1);
    }
}

// ---------------- loss: branch-free lse, scalar coalesced loads ----------------
__global__ void __launch_bounds__(512)
nll_kernel(const float* __restrict__ logits, const int* __restrict__ target,
           float* __restrict__ nll) {
    int row = blockIdx.x;
    const float* lg = logits + (size_t)row * Vv;
    int tid = threadIdx.x;
    float s = 0.f;
    for (int v = tid; v < Vv; v += 512)
        s += __expf(lg[v]);
    __shared__ float red[512];
    red[tid] = s;
    __syncthreads();
    for (int off = 256; off > 0; off >>= 1) {
        if (tid < off) red[tid] += red[tid + off];
        __syncthreads();
    }
    if (tid == 0) {
        float lse = logf(red[0]);
        nll[row] = lse - lg[target[row]];
    }
}

__global__ void loss_reduce_kernel(const float* __restrict__ nll, float* __restrict__ out) {
    __shared__ float red[256];
    int tid = threadIdx.x;
    float s = 0.f;
    for (int i = tid; i < BT; i += 256) s += nll[i];
    red[tid] = s; __syncthreads();
    for (int off = 128; off > 0; off >>= 1) {
        if (tid < off) red[tid] += red[tid + off];
        __syncthreads();
    }
    if (tid == 0) out[0] = red[0] * (1.f / BT);
}

// ---------------- host driver ----------------
extern "C" void kernel_launch(void* const* d_in, const int* in_sizes, int n_in,
                              void* d_out, int out_size) {
    const int* x      = (const int*)d_in[0];
    const int* target = (const int*)d_in[1];
    const float* tok  = (const float*)d_in[2];
    const float* pos  = (const float*)d_in[3];
    const float* ipw  = (const float*)d_in[4];
    const float* ipb  = (const float*)d_in[5];
    const float* wk   = (const float*)d_in[6];
    const float* bk   = (const float*)d_in[7];
    const float* wq   = (const float*)d_in[8];
    const float* bq   = (const float*)d_in[9];
    const float* wv   = (const float*)d_in[10];
    const float* bv   = (const float*)d_in[11];
    const float* opw  = (const float*)d_in[12];
    const float* opb  = (const float*)d_in[13];
    const float* w1   = (const float*)d_in[14];
    const float* b1   = (const float*)d_in[15];
    const float* w2   = (const float*)d_in[16];
    const float* b2   = (const float*)d_in[17];
    const float* lnag = (const float*)d_in[18];
    const float* lnab = (const float*)d_in[19];
    const float* lnfg = (const float*)d_in[20];
    const float* lnfb = (const float*)d_in[21];
    const float* outw = (const float*)d_in[22];
    const float* outb = (const float*)d_in[23];
    float* out = (float*)d_out;

    float *p_x, *p_bqkv, *p_nll, *p_lfb;
    __half *p_ln16, *p_h16, *p_qkv16, *p_attn16, *p_ff16, *p_x16;
    __half *p_wT, *p_ipw, *p_opw, *p_w1, *p_w2, *p_wpad;
    cudaGetSymbolAddress((void**)&p_x, g_x);
    cudaGetSymbolAddress((void**)&p_ln16, g_ln16);
    cudaGetSymbolAddress((void**)&p_h16, g_h16);
    cudaGetSymbolAddress((void**)&p_qkv16, g_qkv16);
    cudaGetSymbolAddress((void**)&p_attn16, g_attn16);
    cudaGetSymbolAddress((void**)&p_ff16, g_ff16);
    cudaGetSymbolAddress((void**)&p_x16, g_x16);
    cudaGetSymbolAddress((void**)&p_wT, g_wT16);
    cudaGetSymbolAddress((void**)&p_ipw, g_ipw16);
    cudaGetSymbolAddress((void**)&p_opw, g_opw16);
    cudaGetSymbolAddress((void**)&p_w1, g_w116);
    cudaGetSymbolAddress((void**)&p_w2, g_w216);
    cudaGetSymbolAddress((void**)&p_wpad, g_wpad16);
    cudaGetSymbolAddress((void**)&p_bqkv, g_bqkv);
    cudaGetSymbolAddress((void**)&p_nll, g_nll);
    cudaGetSymbolAddress((void**)&p_lfb, g_logits_fb);

    constexpr int SM64 = (128 * SAH * 2 + 32 * 72 * 2) * NSTG;     // 74240
    constexpr int SM128 = (128 * SAH * 2 + 32 * 136 * 2) * NSTG;   // 94720
    cudaFuncSetAttribute(hgemm2_kernel<64, false, false, false, true, false>,
                         cudaFuncAttributeMaxDynamicSharedMemorySize, SM64);
    cudaFuncSetAttribute(hgemm2_kernel<64, false, true, false, false, false>,
                         cudaFuncAttributeMaxDynamicSharedMemorySize, SM64);
    cudaFuncSetAttribute(hgemm2_kernel<64, false, true, false, false, true>,
                         cudaFuncAttributeMaxDynamicSharedMemorySize, SM64);
    cudaFuncSetAttribute(hgemm2_kernel<128, false, false, false, true, false>,
                         cudaFuncAttributeMaxDynamicSharedMemorySize, SM128);
    cudaFuncSetAttribute(hgemm2_kernel<128, true, false, false, true, false>,
                         cudaFuncAttributeMaxDynamicSharedMemorySize, SM128);
    cudaFuncSetAttribute(hgemm2_kernel<128, false, false, true, false, false>,
                         cudaFuncAttributeMaxDynamicSharedMemorySize, SM128);

    const size_t BTV = (size_t)BT * Vv;
    float* logits_dst = ((size_t)out_size >= BTV) ? out : p_lfb;

    embed_kernel<<<BT, 256>>>(x, tok, pos, p_x);
    {
        int total = 2 * WSZ1 + 2 * WSZ2;
        cvt_all_kernel<<<(total + 255) / 256, 256>>>(ipw, p_ipw, opw, p_opw,
                                                     w1, p_w1, w2, p_w2);
        int t2v = Dd * VP / 2;
        cvt_pad_kernel<<<(t2v + 255) / 256, 256>>>(outw, p_wpad, Dd, Vv, VP, t2v);
    }
    tqkv16b_kernel<<<dim3(Dd / 64, 3 * Hh, Ll), 256>>>(wq, wk, wv, p_wT);
    bqkv_kernel<<<(Ll * QS + 255) / 256, 256>>>(bq, bk, bv, p_bqkv);

    dim3 gD(16, Dd / 64);       // (16,12)
    dim3 gQ(16, QS / 128);      // (16,18)
    dim3 gF(16, FF / 128);      // (16,24)
    dim3 gV(16, VP / 128);      // (16,394)

    for (int l = 0; l < Ll; l++) {
        ln_kernel<<<BT / 8, 256>>>(p_x, p_ln16, lnag + (size_t)l * Dd, lnab + (size_t)l * Dd);
        hgemm2_kernel<64, false, false, false, true, false><<<gD, 128, SM64>>>(
            Dd, Dd, Dd, Dd, p_ln16, p_ipw + (size_t)l * Dd * Dd, ipb + (size_t)l * Dd,
            nullptr, p_h16, nullptr);

        hgemm2_kernel<128, false, false, false, true, false><<<gQ, 128, SM128>>>(
            QS, Dd, QS, QS, p_h16, p_wT + (size_t)l * Dd * QS, p_bqkv + (size_t)l * QS,
            nullptr, p_qkv16, nullptr);

        flashmma_kernel<<<dim3(Tt / 64, Bb * Hh), 128>>>(p_qkv16, p_attn16);

        hgemm2_kernel<64, false, true, false, false, false><<<gD, 128, SM64>>>(
            Dd, Dd, Dd, Dd, p_attn16, p_opw + (size_t)l * Dd * Dd, opb + (size_t)l * Dd,
            p_x, p_x, nullptr);

        ln_kernel<<<BT / 8, 256>>>(p_x, p_ln16, lnfg + (size_t)l * Dd, lnfb + (size_t)l * Dd);
        hgemm2_kernel<128, true, false, false, true, false><<<gF, 128, SM128>>>(
            FF, Dd, FF, FF, p_ln16, p_w1 + (size_t)l * Dd * FF, b1 + (size_t)l * FF,
            nullptr, p_ff16, nullptr);
        if (l == Ll - 1) {
            hgemm2_kernel<64, false, true, false, false, true><<<gD, 128, SM64>>>(
                Dd, FF, Dd, Dd, p_ff16, p_w2 + (size_t)l * FF * Dd, b2 + (size_t)l * Dd,
                p_x, p_x, p_x16);
        } else {
            hgemm2_kernel<64, false, true, false, false, false><<<gD, 128, SM64>>>(
                Dd, FF, Dd, Dd, p_ff16, p_w2 + (size_t)l * FF * Dd, b2 + (size_t)l * Dd,
                p_x, p_x, nullptr);
        }
    }

    hgemm2_kernel<128, false, false, true, false, false><<<gV, 128, SM128>>>(
        Vv, Dd, VP, Vv, p_x16, p_wpad, outb, nullptr, logits_dst, nullptr);

    nll_kernel<<<BT, 512>>>(logits_dst, target, p_nll);
    if ((size_t)out_size > BTV) {
        loss_reduce_kernel<<<1, 256>>>(p_nll, out + BTV);
    } else if (out_size == 1) {
        loss_reduce_kernel<<<1, 256>>>(p_nll, out);
    }
}